// round 5
// baseline (speedup 1.0000x reference)
#include <cuda_runtime.h>
#include <math.h>

#define NN 50000
#define EE 1600000
#define GG 512
#define INF 16
#define HH 128

// ---- scratch (static device memory; no allocation anywhere) ----
__device__ float g_bufA[NN * HH];   // gemm outputs
__device__ float g_bufB[NN * HH];   // aggregated layer outputs
__device__ int   g_degi[NN];        // in-degree (edges only)
__device__ int   g_off[NN];         // CSR offsets
__device__ int   g_cur[NN];         // fill cursors
__device__ int   g_csr[EE];         // src ids grouped by dst
__device__ float g_dinv[NN];

__global__ void k_init() {
    int i = blockIdx.x * blockDim.x + threadIdx.x;
    if (i < NN) { g_degi[i] = 0; g_cur[i] = 0; }
}

__global__ void k_deg(const int* __restrict__ ei) {
    int e = blockIdx.x * blockDim.x + threadIdx.x;
    if (e < EE) atomicAdd(&g_degi[ei[EE + e]], 1);
}

// single-block exclusive scan of g_degi -> g_off; dinv = rsqrt(deg+1)
__global__ void k_scan() {
    __shared__ int sums[1024];
    const int per = (NN + 1023) / 1024;
    int t = threadIdx.x;
    int base = t * per;
    int local = 0;
    for (int i = 0; i < per; i++) {
        int idx = base + i;
        if (idx < NN) local += g_degi[idx];
    }
    sums[t] = local;
    __syncthreads();
    for (int off = 1; off < 1024; off <<= 1) {
        int v = (t >= off) ? sums[t - off] : 0;
        __syncthreads();
        sums[t] += v;
        __syncthreads();
    }
    int start = (t == 0) ? 0 : sums[t - 1];
    for (int i = 0; i < per; i++) {
        int idx = base + i;
        if (idx < NN) {
            g_off[idx] = start;
            int d = g_degi[idx];
            start += d;
            g_dinv[idx] = rsqrtf((float)(d + 1));
        }
    }
}

__global__ void k_fill(const int* __restrict__ ei) {
    int e = blockIdx.x * blockDim.x + threadIdx.x;
    if (e >= EE) return;
    int s = ei[e];
    int d = ei[EE + e];
    int pos = atomicAdd(&g_cur[d], 1);
    g_csr[g_off[d] + pos] = s;
}

// x[N,16] @ W1[16,128] -> g_bufA   (8 nodes per 256-thread block)
__global__ void k_gemm1(const float* __restrict__ x, const float* __restrict__ W1) {
    __shared__ float sW[INF * HH];
    int t = threadIdx.x;
    for (int i = t; i < INF * HH; i += blockDim.x) sW[i] = W1[i];
    __syncthreads();
    int lane = t & 31, nl = t >> 5;
    int node = blockIdx.x * 8 + nl;
    if (node >= NN) return;
    float4 acc = make_float4(0.f, 0.f, 0.f, 0.f);
    const float* xr = x + node * INF;
    #pragma unroll
    for (int k = 0; k < INF; k++) {
        float xv = xr[k];
        float4 w = *(const float4*)&sW[k * HH + lane * 4];
        acc.x += xv * w.x; acc.y += xv * w.y;
        acc.z += xv * w.z; acc.w += xv * w.w;
    }
    *(float4*)&g_bufA[node * HH + lane * 4] = acc;
}

// warp per node: g_bufB[n] = relu( sum_e norm*g_bufA[src] + dinv^2*g_bufA[n] + b )
__global__ void k_agg(const float* __restrict__ b) {
    int wid = (blockIdx.x * blockDim.x + threadIdx.x) >> 5;
    int lane = threadIdx.x & 31;
    if (wid >= NN) return;
    int off = g_off[wid];
    int deg = g_degi[wid];
    float di = g_dinv[wid];

    float4 h = *(const float4*)&g_bufA[wid * HH + lane * 4];
    float wl = di * di;
    float4 acc = make_float4(h.x * wl, h.y * wl, h.z * wl, h.w * wl);

    int j = 0;
    for (; j + 4 <= deg; j += 4) {
        int s0 = g_csr[off + j + 0];
        int s1 = g_csr[off + j + 1];
        int s2 = g_csr[off + j + 2];
        int s3 = g_csr[off + j + 3];
        float w0 = di * g_dinv[s0];
        float w1 = di * g_dinv[s1];
        float w2 = di * g_dinv[s2];
        float w3 = di * g_dinv[s3];
        float4 v0 = *(const float4*)&g_bufA[s0 * HH + lane * 4];
        float4 v1 = *(const float4*)&g_bufA[s1 * HH + lane * 4];
        float4 v2 = *(const float4*)&g_bufA[s2 * HH + lane * 4];
        float4 v3 = *(const float4*)&g_bufA[s3 * HH + lane * 4];
        acc.x += w0 * v0.x + w1 * v1.x + w2 * v2.x + w3 * v3.x;
        acc.y += w0 * v0.y + w1 * v1.y + w2 * v2.y + w3 * v3.y;
        acc.z += w0 * v0.z + w1 * v1.z + w2 * v2.z + w3 * v3.z;
        acc.w += w0 * v0.w + w1 * v1.w + w2 * v2.w + w3 * v3.w;
    }
    for (; j < deg; j++) {
        int s = g_csr[off + j];
        float w = di * g_dinv[s];
        float4 v = *(const float4*)&g_bufA[s * HH + lane * 4];
        acc.x += w * v.x; acc.y += w * v.y;
        acc.z += w * v.z; acc.w += w * v.w;
    }

    float4 bv = *(const float4*)&b[lane * 4];
    acc.x = fmaxf(acc.x + bv.x, 0.f);
    acc.y = fmaxf(acc.y + bv.y, 0.f);
    acc.z = fmaxf(acc.z + bv.z, 0.f);
    acc.w = fmaxf(acc.w + bv.w, 0.f);
    *(float4*)&g_bufB[wid * HH + lane * 4] = acc;
}

// g_bufB[N,128] @ W[128,128] -> g_bufA. 256 thr, 32 nodes/block, 2-pass 32KB smem.
__global__ void k_gemm2(const float* __restrict__ W) {
    __shared__ float sW[64 * HH];
    int t = threadIdx.x;
    int lane = t & 31, warp = t >> 5;
    int nb = blockIdx.x * 32 + warp * 4;

    float4 acc[4];
    #pragma unroll
    for (int n = 0; n < 4; n++) acc[n] = make_float4(0.f, 0.f, 0.f, 0.f);

    int nidx[4];
    #pragma unroll
    for (int n = 0; n < 4; n++) {
        int node = nb + n;
        nidx[n] = node < NN ? node : NN - 1;
    }

    for (int p = 0; p < 2; p++) {
        for (int i = t * 4; i < 64 * HH; i += blockDim.x * 4)
            *(float4*)&sW[i] = *(const float4*)&W[p * 64 * HH + i];
        __syncthreads();
        for (int k = 0; k < 64; k += 4) {
            float4 w0 = *(const float4*)&sW[(k + 0) * HH + lane * 4];
            float4 w1 = *(const float4*)&sW[(k + 1) * HH + lane * 4];
            float4 w2 = *(const float4*)&sW[(k + 2) * HH + lane * 4];
            float4 w3 = *(const float4*)&sW[(k + 3) * HH + lane * 4];
            #pragma unroll
            for (int n = 0; n < 4; n++) {
                float4 h = *(const float4*)&g_bufB[nidx[n] * HH + p * 64 + k];
                acc[n].x += h.x * w0.x + h.y * w1.x + h.z * w2.x + h.w * w3.x;
                acc[n].y += h.x * w0.y + h.y * w1.y + h.z * w2.y + h.w * w3.y;
                acc[n].z += h.x * w0.z + h.y * w1.z + h.z * w2.z + h.w * w3.z;
                acc[n].w += h.x * w0.w + h.y * w1.w + h.z * w2.w + h.w * w3.w;
            }
        }
        __syncthreads();
    }
    #pragma unroll
    for (int n = 0; n < 4; n++) {
        int node = nb + n;
        if (node < NN) *(float4*)&g_bufA[node * HH + lane * 4] = acc[n];
    }
}

// One block (128 thr) per graph. batch is SORTED int32: binary search the
// graph's node segment, segmented mean over g_bufB, then both heads fused.
__global__ void k_poolhead(const int* __restrict__ batch,
                           const float* __restrict__ Wlab, const float* __restrict__ blab,
                           const float* __restrict__ Wd1, const float* __restrict__ bd1,
                           const float* __restrict__ Wd2, const float* __restrict__ bd2,
                           float* __restrict__ out) {
    __shared__ float p[HH];
    __shared__ float hid[64];
    __shared__ float warpsum[4];
    int g = blockIdx.x, t = threadIdx.x;

    // first index with batch[i] >= g
    int lo = 0, hi = NN;
    while (lo < hi) { int m = (lo + hi) >> 1; if (batch[m] < g) lo = m + 1; else hi = m; }
    int start = lo;
    // first index with batch[i] >= g+1
    hi = NN;
    while (lo < hi) { int m = (lo + hi) >> 1; if (batch[m] < g + 1) lo = m + 1; else hi = m; }
    int end = lo;

    float s = 0.f;
    for (int n = start; n < end; n++) s += g_bufB[n * HH + t];
    float c = fmaxf((float)(end - start), 1.0f);
    float pv = s / c;
    p[t] = pv;

    // label head: dot(p, Wlab) via shuffle reduction
    float l = pv * Wlab[t];
    #pragma unroll
    for (int o = 16; o; o >>= 1) l += __shfl_xor_sync(0xffffffffu, l, o);
    if ((t & 31) == 0) warpsum[t >> 5] = l;
    __syncthreads();

    if (t < 64) {
        float h2 = bd1[t];
        #pragma unroll 4
        for (int k = 0; k < HH; k++) h2 += p[k] * Wd1[k * 64 + t];
        hid[t] = fmaxf(h2, 0.f);
    }
    __syncthreads();

    if (t == 0) {
        float z = warpsum[0] + warpsum[1] + warpsum[2] + warpsum[3] + blab[0];
        out[g] = 1.0f / (1.0f + expf(-z));
    }
    if (t < 2) {
        float s2 = bd2[t];
        #pragma unroll
        for (int k = 0; k < 64; k++) s2 += hid[k] * Wd2[k * 2 + t];
        out[GG + g * 2 + t] = s2;
    }
}

extern "C" void kernel_launch(void* const* d_in, const int* in_sizes, int n_in,
                              void* d_out, int out_size) {
    const float* x     = (const float*)d_in[0];
    const int*   ei    = (const int*)d_in[1];     // int32! (JAX x64 disabled)
    const int*   batch = (const int*)d_in[2];     // int32!
    const float* W1    = (const float*)d_in[3];
    const float* b1    = (const float*)d_in[4];
    const float* W2    = (const float*)d_in[5];
    const float* b2    = (const float*)d_in[6];
    const float* Wlab  = (const float*)d_in[7];
    const float* blab  = (const float*)d_in[8];
    const float* Wd1   = (const float*)d_in[9];
    const float* bd1   = (const float*)d_in[10];
    const float* Wd2   = (const float*)d_in[11];
    const float* bd2   = (const float*)d_in[12];
    float* out = (float*)d_out;

    const int T = 256;
    // CSR build + norms
    k_init<<<(NN + T - 1) / T, T>>>();
    k_deg<<<(EE + T - 1) / T, T>>>(ei);
    k_scan<<<1, 1024>>>();
    k_fill<<<(EE + T - 1) / T, T>>>(ei);

    // layer 1
    k_gemm1<<<(NN + 7) / 8, T>>>(x, W1);
    k_agg<<<(NN * 32 + T - 1) / T, T>>>(b1);

    // layer 2
    k_gemm2<<<(NN + 31) / 32, T>>>(W2);
    k_agg<<<(NN * 32 + T - 1) / T, T>>>(b2);

    // pooling + heads (no atomics; batch is sorted)
    k_poolhead<<<GG, HH>>>(batch, Wlab, blab, Wd1, bd1, Wd2, bd2, out);
}

// round 6
// speedup vs baseline: 1.6224x; 1.6224x over previous
#include <cuda_runtime.h>
#include <cuda_fp16.h>
#include <math.h>

#define NN 50000
#define EE 1600000
#define GG 512
#define INF 16
#define HH 128
#define NBLK 49   // ceil(50000/1024)

// ---- scratch (static device memory; no allocation anywhere) ----
__device__ __half g_half[NN * HH];  // dinv-prescaled features (gather source)
__device__ float  g_bufB[NN * HH];  // fp32 layer outputs
__device__ int    g_degi[NN];
__device__ int    g_off[NN];
__device__ int    g_cur[NN];
__device__ int    g_csr[EE];
__device__ float  g_dinv[NN];
__device__ int    g_bsum[NBLK];
__device__ int    g_boff[NBLK];

// ---------- f32x2 helpers ----------
__device__ __forceinline__ unsigned long long pack2(float v) {
    unsigned long long r;
    asm("mov.b64 %0, {%1, %1};" : "=l"(r) : "r"(__float_as_uint(v)));
    return r;
}
__device__ __forceinline__ unsigned long long fma2(unsigned long long a,
                                                   unsigned long long b,
                                                   unsigned long long c) {
    unsigned long long d;
    asm("fma.rn.f32x2 %0, %1, %2, %3;" : "=l"(d) : "l"(a), "l"(b), "l"(c));
    return d;
}
__device__ __forceinline__ float2 unpack2(unsigned long long v) {
    unsigned lo, hi;
    asm("mov.b64 {%0, %1}, %2;" : "=r"(lo), "=r"(hi) : "l"(v));
    return make_float2(__uint_as_float(lo), __uint_as_float(hi));
}
// load 4 halfs -> float4
__device__ __forceinline__ float4 ldh4(const __half* p) {
    uint2 u = *(const uint2*)p;
    __half2 a, b;
    *(unsigned*)&a = u.x; *(unsigned*)&b = u.y;
    float2 fa = __half22float2(a), fb = __half22float2(b);
    return make_float4(fa.x, fa.y, fb.x, fb.y);
}
__device__ __forceinline__ void sth4(__half* p, float4 v) {
    __half2 a = __floats2half2_rn(v.x, v.y);
    __half2 b = __floats2half2_rn(v.z, v.w);
    uint2 u;
    u.x = *(unsigned*)&a; u.y = *(unsigned*)&b;
    *(uint2*)p = u;
}

__global__ void k_init() {
    int i = blockIdx.x * blockDim.x + threadIdx.x;
    if (i < NN) g_degi[i] = 0;
}

__global__ void k_deg(const int* __restrict__ ei) {
    int e = blockIdx.x * blockDim.x + threadIdx.x;
    if (e < EE) atomicAdd(&g_degi[ei[EE + e]], 1);
}

// 49 blocks: coalesced int4 partial sums of g_degi
__global__ void k_bsum() {
    __shared__ int sred[256];
    int b = blockIdx.x, t = threadIdx.x;
    int base = b * 1024 + t * 4;
    int s = 0;
    if (base + 3 < NN) {
        int4 q = *(const int4*)&g_degi[base];
        s = q.x + q.y + q.z + q.w;
    } else {
        for (int i = 0; i < 4; i++) if (base + i < NN) s += g_degi[base + i];
    }
    sred[t] = s;
    __syncthreads();
    for (int o = 128; o; o >>= 1) {
        if (t < o) sred[t] += sred[t + o];
        __syncthreads();
    }
    if (t == 0) g_bsum[b] = sred[0];
}

// exclusive scan of the 49 block sums
__global__ void k_bscan() {
    __shared__ int s[64];
    int t = threadIdx.x;
    int v = (t < NBLK) ? g_bsum[t] : 0;
    s[t] = v;
    __syncthreads();
    for (int o = 1; o < 64; o <<= 1) {
        int x = (t >= o) ? s[t - o] : 0;
        __syncthreads();
        s[t] += x;
        __syncthreads();
    }
    if (t < NBLK) g_boff[t] = s[t] - v;
}

// per-block scan -> g_off, g_cur (absolute cursors), g_dinv
__global__ void k_offsets() {
    __shared__ int spart[256];
    int b = blockIdx.x, t = threadIdx.x;
    int base = b * 1024 + t * 4;
    int d0 = 0, d1 = 0, d2 = 0, d3 = 0;
    if (base + 3 < NN) {
        int4 q = *(const int4*)&g_degi[base];
        d0 = q.x; d1 = q.y; d2 = q.z; d3 = q.w;
    } else {
        if (base + 0 < NN) d0 = g_degi[base + 0];
        if (base + 1 < NN) d1 = g_degi[base + 1];
        if (base + 2 < NN) d2 = g_degi[base + 2];
        if (base + 3 < NN) d3 = g_degi[base + 3];
    }
    int tot = d0 + d1 + d2 + d3;
    spart[t] = tot;
    __syncthreads();
    for (int o = 1; o < 256; o <<= 1) {
        int x = (t >= o) ? spart[t - o] : 0;
        __syncthreads();
        spart[t] += x;
        __syncthreads();
    }
    int off = g_boff[b] + spart[t] - tot;
    int dd[4] = {d0, d1, d2, d3};
    #pragma unroll
    for (int i = 0; i < 4; i++) {
        int idx = base + i;
        if (idx < NN) {
            g_off[idx] = off;
            g_cur[idx] = off;
            g_dinv[idx] = rsqrtf((float)(dd[i] + 1));
            off += dd[i];
        }
    }
}

__global__ void k_fill(const int* __restrict__ ei) {
    int e = blockIdx.x * blockDim.x + threadIdx.x;
    if (e >= EE) return;
    int s = ei[e];
    int d = ei[EE + e];
    int pos = atomicAdd(&g_cur[d], 1);
    g_csr[pos] = s;
}

// x[N,16] @ W1[16,128], prescale by dinv, write half
__global__ void k_gemm1(const float* __restrict__ x, const float* __restrict__ W1) {
    __shared__ float sW[INF * HH];
    int t = threadIdx.x;
    for (int i = t; i < INF * HH; i += blockDim.x) sW[i] = W1[i];
    __syncthreads();
    int lane = t & 31, nl = t >> 5;
    int node = blockIdx.x * 8 + nl;
    if (node >= NN) return;
    float4 acc = make_float4(0.f, 0.f, 0.f, 0.f);
    const float* xr = x + node * INF;
    #pragma unroll
    for (int k = 0; k < INF; k++) {
        float xv = xr[k];
        float4 w = *(const float4*)&sW[k * HH + lane * 4];
        acc.x += xv * w.x; acc.y += xv * w.y;
        acc.z += xv * w.z; acc.w += xv * w.w;
    }
    float di = g_dinv[node];
    acc.x *= di; acc.y *= di; acc.z *= di; acc.w *= di;
    sth4(&g_half[node * HH + lane * 4], acc);
}

// warp per node: bufB[n] = relu( di * (sum_src S'[src] + S'[n]) + b )
// where S' = dinv-prescaled half features. Pure sum — no per-edge weights.
__global__ void k_agg(const float* __restrict__ b) {
    int wid = (blockIdx.x * blockDim.x + threadIdx.x) >> 5;
    int lane = threadIdx.x & 31;
    if (wid >= NN) return;
    int off = g_off[wid];
    int deg = g_degi[wid];
    float di = g_dinv[wid];

    float4 acc = ldh4(&g_half[wid * HH + lane * 4]);  // self term (pre-scaled)

    int j = 0;
    for (; j + 4 <= deg; j += 4) {
        int s0 = g_csr[off + j + 0];
        int s1 = g_csr[off + j + 1];
        int s2 = g_csr[off + j + 2];
        int s3 = g_csr[off + j + 3];
        float4 v0 = ldh4(&g_half[s0 * HH + lane * 4]);
        float4 v1 = ldh4(&g_half[s1 * HH + lane * 4]);
        float4 v2 = ldh4(&g_half[s2 * HH + lane * 4]);
        float4 v3 = ldh4(&g_half[s3 * HH + lane * 4]);
        acc.x += (v0.x + v1.x) + (v2.x + v3.x);
        acc.y += (v0.y + v1.y) + (v2.y + v3.y);
        acc.z += (v0.z + v1.z) + (v2.z + v3.z);
        acc.w += (v0.w + v1.w) + (v2.w + v3.w);
    }
    for (; j < deg; j++) {
        int s = g_csr[off + j];
        float4 v = ldh4(&g_half[s * HH + lane * 4]);
        acc.x += v.x; acc.y += v.y; acc.z += v.z; acc.w += v.w;
    }

    float4 bv = *(const float4*)&b[lane * 4];
    acc.x = fmaxf(di * acc.x + bv.x, 0.f);
    acc.y = fmaxf(di * acc.y + bv.y, 0.f);
    acc.z = fmaxf(di * acc.z + bv.z, 0.f);
    acc.w = fmaxf(di * acc.w + bv.w, 0.f);
    *(float4*)&g_bufB[wid * HH + lane * 4] = acc;
}

// bufB[N,128] @ W2[128,128] -> g_half (dinv-prescaled). f32x2 math.
__global__ void k_gemm2(const float* __restrict__ W) {
    __shared__ float sW[64 * HH];   // 32 KB, 2 passes
    int t = threadIdx.x;
    int lane = t & 31, warp = t >> 5;
    int nb = blockIdx.x * 32 + warp * 4;

    unsigned long long acc[4][2];
    #pragma unroll
    for (int n = 0; n < 4; n++) { acc[n][0] = 0ull; acc[n][1] = 0ull; }

    int nidx[4];
    #pragma unroll
    for (int n = 0; n < 4; n++) {
        int node = nb + n;
        nidx[n] = node < NN ? node : NN - 1;
    }

    for (int p = 0; p < 2; p++) {
        for (int i = t * 4; i < 64 * HH; i += blockDim.x * 4)
            *(float4*)&sW[i] = *(const float4*)&W[p * 64 * HH + i];
        __syncthreads();
        for (int k = 0; k < 64; k += 4) {
            float4 h[4];
            #pragma unroll
            for (int n = 0; n < 4; n++)
                h[n] = *(const float4*)&g_bufB[nidx[n] * HH + p * 64 + k];
            #pragma unroll
            for (int kk = 0; kk < 4; kk++) {
                ulonglong2 w = *(const ulonglong2*)&sW[(k + kk) * HH + lane * 4];
                #pragma unroll
                for (int n = 0; n < 4; n++) {
                    float hv = kk == 0 ? h[n].x : kk == 1 ? h[n].y : kk == 2 ? h[n].z : h[n].w;
                    unsigned long long hh = pack2(hv);
                    acc[n][0] = fma2(hh, w.x, acc[n][0]);
                    acc[n][1] = fma2(hh, w.y, acc[n][1]);
                }
            }
        }
        __syncthreads();
    }
    #pragma unroll
    for (int n = 0; n < 4; n++) {
        int node = nb + n;
        if (node < NN) {
            float di = g_dinv[node];
            float2 lo = unpack2(acc[n][0]);
            float2 hi = unpack2(acc[n][1]);
            float4 v = make_float4(di * lo.x, di * lo.y, di * hi.x, di * hi.y);
            sth4(&g_half[node * HH + lane * 4], v);
        }
    }
}

// One block (128 thr) per graph: sorted-batch segmented mean + both heads.
__global__ void k_poolhead(const int* __restrict__ batch,
                           const float* __restrict__ Wlab, const float* __restrict__ blab,
                           const float* __restrict__ Wd1, const float* __restrict__ bd1,
                           const float* __restrict__ Wd2, const float* __restrict__ bd2,
                           float* __restrict__ out) {
    __shared__ float p[HH];
    __shared__ float hid[64];
    __shared__ float warpsum[4];
    int g = blockIdx.x, t = threadIdx.x;

    int lo = 0, hi = NN;
    while (lo < hi) { int m = (lo + hi) >> 1; if (batch[m] < g) lo = m + 1; else hi = m; }
    int start = lo;
    hi = NN;
    while (lo < hi) { int m = (lo + hi) >> 1; if (batch[m] < g + 1) lo = m + 1; else hi = m; }
    int end = lo;

    float s = 0.f;
    for (int n = start; n < end; n++) s += g_bufB[n * HH + t];
    float c = fmaxf((float)(end - start), 1.0f);
    float pv = s / c;
    p[t] = pv;

    float l = pv * Wlab[t];
    #pragma unroll
    for (int o = 16; o; o >>= 1) l += __shfl_xor_sync(0xffffffffu, l, o);
    if ((t & 31) == 0) warpsum[t >> 5] = l;
    __syncthreads();

    if (t < 64) {
        float h2 = bd1[t];
        #pragma unroll 4
        for (int k = 0; k < HH; k++) h2 += p[k] * Wd1[k * 64 + t];
        hid[t] = fmaxf(h2, 0.f);
    }
    __syncthreads();

    if (t == 0) {
        float z = warpsum[0] + warpsum[1] + warpsum[2] + warpsum[3] + blab[0];
        out[g] = 1.0f / (1.0f + expf(-z));
    }
    if (t < 2) {
        float s2 = bd2[t];
        #pragma unroll
        for (int k = 0; k < 64; k++) s2 += hid[k] * Wd2[k * 2 + t];
        out[GG + g * 2 + t] = s2;
    }
}

extern "C" void kernel_launch(void* const* d_in, const int* in_sizes, int n_in,
                              void* d_out, int out_size) {
    const float* x     = (const float*)d_in[0];
    const int*   ei    = (const int*)d_in[1];     // int32 (JAX x64 disabled)
    const int*   batch = (const int*)d_in[2];     // int32
    const float* W1    = (const float*)d_in[3];
    const float* b1    = (const float*)d_in[4];
    const float* W2    = (const float*)d_in[5];
    const float* b2    = (const float*)d_in[6];
    const float* Wlab  = (const float*)d_in[7];
    const float* blab  = (const float*)d_in[8];
    const float* Wd1   = (const float*)d_in[9];
    const float* bd1   = (const float*)d_in[10];
    const float* Wd2   = (const float*)d_in[11];
    const float* bd2   = (const float*)d_in[12];
    float* out = (float*)d_out;

    const int T = 256;
    // CSR build + norms (coalesced hierarchical scan)
    k_init<<<(NN + T - 1) / T, T>>>();
    k_deg<<<(EE + T - 1) / T, T>>>(ei);
    k_bsum<<<NBLK, T>>>();
    k_bscan<<<1, 64>>>();
    k_offsets<<<NBLK, T>>>();
    k_fill<<<(EE + T - 1) / T, T>>>(ei);

    // layer 1
    k_gemm1<<<(NN + 7) / 8, T>>>(x, W1);
    k_agg<<<(NN * 32 + T - 1) / T, T>>>(b1);

    // layer 2
    k_gemm2<<<(NN + 31) / 32, T>>>(W2);
    k_agg<<<(NN * 32 + T - 1) / T, T>>>(b2);

    // pooling + heads
    k_poolhead<<<GG, HH>>>(batch, Wlab, blab, Wd1, bd1, Wd2, bd2, out);
}

// round 7
// speedup vs baseline: 1.8164x; 1.1195x over previous
#include <cuda_runtime.h>
#include <cuda_fp16.h>
#include <math.h>

#define NN 50000
#define EE 1600000
#define GG 512
#define INF 16
#define HH 128
#define NBLK 49   // ceil(50000/1024)

// ---- scratch (static device memory; no allocation anywhere) ----
__device__ __half g_x16[NN * INF];  // dinv-prescaled input features
__device__ __half g_half[NN * HH];  // dinv-prescaled h1 (gather source, layer 2)
__device__ float  g_bufB[NN * HH];  // fp32 aggregate / layer-2 output
__device__ int    g_degi[NN];
__device__ int    g_off[NN];
__device__ int    g_cur[NN];
__device__ int    g_csr[EE];
__device__ float  g_dinv[NN];
__device__ int    g_bsum[NBLK];
__device__ int    g_boff[NBLK];

// ---------- f32x2 helpers ----------
__device__ __forceinline__ unsigned long long pack2(float v) {
    unsigned long long r;
    asm("mov.b64 %0, {%1, %1};" : "=l"(r) : "r"(__float_as_uint(v)));
    return r;
}
__device__ __forceinline__ unsigned long long fma2(unsigned long long a,
                                                   unsigned long long b,
                                                   unsigned long long c) {
    unsigned long long d;
    asm("fma.rn.f32x2 %0, %1, %2, %3;" : "=l"(d) : "l"(a), "l"(b), "l"(c));
    return d;
}
__device__ __forceinline__ float2 unpack2(unsigned long long v) {
    unsigned lo, hi;
    asm("mov.b64 {%0, %1}, %2;" : "=r"(lo), "=r"(hi) : "l"(v));
    return make_float2(__uint_as_float(lo), __uint_as_float(hi));
}
__device__ __forceinline__ float4 ldh4(const __half* p) {
    uint2 u = *(const uint2*)p;
    __half2 a, b;
    *(unsigned*)&a = u.x; *(unsigned*)&b = u.y;
    float2 fa = __half22float2(a), fb = __half22float2(b);
    return make_float4(fa.x, fa.y, fb.x, fb.y);
}
__device__ __forceinline__ void sth4(__half* p, float4 v) {
    __half2 a = __floats2half2_rn(v.x, v.y);
    __half2 b = __floats2half2_rn(v.z, v.w);
    uint2 u;
    u.x = *(unsigned*)&a; u.y = *(unsigned*)&b;
    *(uint2*)p = u;
}

__global__ void k_init() {
    int i = blockIdx.x * blockDim.x + threadIdx.x;
    if (i < NN) g_degi[i] = 0;
}

__global__ void k_deg(const int* __restrict__ ei) {
    int e = blockIdx.x * blockDim.x + threadIdx.x;
    if (e < EE) atomicAdd(&g_degi[ei[EE + e]], 1);
}

// 49 blocks: coalesced int4 partial sums of g_degi
__global__ void k_bsum() {
    __shared__ int sred[256];
    int b = blockIdx.x, t = threadIdx.x;
    int base = b * 1024 + t * 4;
    int s = 0;
    if (base + 3 < NN) {
        int4 q = *(const int4*)&g_degi[base];
        s = q.x + q.y + q.z + q.w;
    } else {
        for (int i = 0; i < 4; i++) if (base + i < NN) s += g_degi[base + i];
    }
    sred[t] = s;
    __syncthreads();
    for (int o = 128; o; o >>= 1) {
        if (t < o) sred[t] += sred[t + o];
        __syncthreads();
    }
    if (t == 0) g_bsum[b] = sred[0];
}

__global__ void k_bscan() {
    __shared__ int s[64];
    int t = threadIdx.x;
    int v = (t < NBLK) ? g_bsum[t] : 0;
    s[t] = v;
    __syncthreads();
    for (int o = 1; o < 64; o <<= 1) {
        int x = (t >= o) ? s[t - o] : 0;
        __syncthreads();
        s[t] += x;
        __syncthreads();
    }
    if (t < NBLK) g_boff[t] = s[t] - v;
}

__global__ void k_offsets() {
    __shared__ int spart[256];
    int b = blockIdx.x, t = threadIdx.x;
    int base = b * 1024 + t * 4;
    int d0 = 0, d1 = 0, d2 = 0, d3 = 0;
    if (base + 3 < NN) {
        int4 q = *(const int4*)&g_degi[base];
        d0 = q.x; d1 = q.y; d2 = q.z; d3 = q.w;
    } else {
        if (base + 0 < NN) d0 = g_degi[base + 0];
        if (base + 1 < NN) d1 = g_degi[base + 1];
        if (base + 2 < NN) d2 = g_degi[base + 2];
        if (base + 3 < NN) d3 = g_degi[base + 3];
    }
    int tot = d0 + d1 + d2 + d3;
    spart[t] = tot;
    __syncthreads();
    for (int o = 1; o < 256; o <<= 1) {
        int x = (t >= o) ? spart[t - o] : 0;
        __syncthreads();
        spart[t] += x;
        __syncthreads();
    }
    int off = g_boff[b] + spart[t] - tot;
    int dd[4] = {d0, d1, d2, d3};
    #pragma unroll
    for (int i = 0; i < 4; i++) {
        int idx = base + i;
        if (idx < NN) {
            g_off[idx] = off;
            g_cur[idx] = off;
            g_dinv[idx] = rsqrtf((float)(dd[i] + 1));
            off += dd[i];
        }
    }
}

__global__ void k_fill(const int* __restrict__ ei) {
    int e = blockIdx.x * blockDim.x + threadIdx.x;
    if (e >= EE) return;
    int s = ei[e];
    int d = ei[EE + e];
    int pos = atomicAdd(&g_cur[d], 1);
    g_csr[pos] = s;
}

// x' = dinv * x, fp16  (thread = one half2 pair)
__global__ void k_prex(const float* __restrict__ x) {
    int i = blockIdx.x * blockDim.x + threadIdx.x;
    if (i >= NN * 8) return;
    int node = i >> 3;
    float2 v = *(const float2*)&x[i * 2];
    float di = g_dinv[node];
    __half2 h = __floats2half2_rn(v.x * di, v.y * di);
    *(__half2*)&g_x16[i * 2] = h;
}

// warp per node: a = di*(sum_src x'[s] + x'[n]) [16-dim], then
// h1 = relu(a @ W1 + b1), store di*h1 as fp16 -> g_half.
// Lane layout: grp = lane>>3 handles edge j+grp; p = lane&7 is the half2 pair.
__global__ void k_agg16(const float* __restrict__ W1, const float* __restrict__ b1) {
    __shared__ float sW[INF * HH];   // 8 KB
    int t = threadIdx.x;
    for (int i = t; i < INF * HH; i += blockDim.x) sW[i] = W1[i];
    __syncthreads();

    int wid = (blockIdx.x * blockDim.x + t) >> 5;
    if (wid >= NN) return;
    int lane = t & 31;
    int grp = lane >> 3, p = lane & 7;
    int off = g_off[wid];
    int deg = g_degi[wid];
    float di = g_dinv[wid];

    float2 acc = make_float2(0.f, 0.f);
    if (grp == 0)
        acc = __half22float2(*(const __half2*)&g_x16[wid * INF + 2 * p]);

    for (int j = grp; j < deg; j += 4) {
        int s = g_csr[off + j];
        float2 v = __half22float2(*(const __half2*)&g_x16[s * INF + 2 * p]);
        acc.x += v.x; acc.y += v.y;
    }
    // sum the 4 groups (xor 8, 16 preserve p = lane&7)
    acc.x += __shfl_xor_sync(0xffffffffu, acc.x, 8);
    acc.y += __shfl_xor_sync(0xffffffffu, acc.y, 8);
    acc.x += __shfl_xor_sync(0xffffffffu, acc.x, 16);
    acc.y += __shfl_xor_sync(0xffffffffu, acc.y, 16);
    acc.x *= di; acc.y *= di;

    // gemm: lane computes output cols 4*lane .. 4*lane+3
    float4 out = *(const float4*)&b1[lane * 4];
    #pragma unroll
    for (int k = 0; k < 8; k++) {
        float ax = __shfl_sync(0xffffffffu, acc.x, k);
        float ay = __shfl_sync(0xffffffffu, acc.y, k);
        float4 w0 = *(const float4*)&sW[(2 * k) * HH + lane * 4];
        float4 w1 = *(const float4*)&sW[(2 * k + 1) * HH + lane * 4];
        out.x += ax * w0.x + ay * w1.x;
        out.y += ax * w0.y + ay * w1.y;
        out.z += ax * w0.z + ay * w1.z;
        out.w += ax * w0.w + ay * w1.w;
    }
    out.x = fmaxf(out.x, 0.f) * di;
    out.y = fmaxf(out.y, 0.f) * di;
    out.z = fmaxf(out.z, 0.f) * di;
    out.w = fmaxf(out.w, 0.f) * di;
    sth4(&g_half[wid * HH + lane * 4], out);
}

// warp per node: bufB[n] = di * (sum_src h1'[s] + h1'[n])   (128-dim, fp32)
__global__ void k_agg128() {
    int wid = (blockIdx.x * blockDim.x + threadIdx.x) >> 5;
    int lane = threadIdx.x & 31;
    if (wid >= NN) return;
    int off = g_off[wid];
    int deg = g_degi[wid];
    float di = g_dinv[wid];

    float4 acc = ldh4(&g_half[wid * HH + lane * 4]);

    int j = 0;
    for (; j + 4 <= deg; j += 4) {
        int s0 = g_csr[off + j + 0];
        int s1 = g_csr[off + j + 1];
        int s2 = g_csr[off + j + 2];
        int s3 = g_csr[off + j + 3];
        float4 v0 = ldh4(&g_half[s0 * HH + lane * 4]);
        float4 v1 = ldh4(&g_half[s1 * HH + lane * 4]);
        float4 v2 = ldh4(&g_half[s2 * HH + lane * 4]);
        float4 v3 = ldh4(&g_half[s3 * HH + lane * 4]);
        acc.x += (v0.x + v1.x) + (v2.x + v3.x);
        acc.y += (v0.y + v1.y) + (v2.y + v3.y);
        acc.z += (v0.z + v1.z) + (v2.z + v3.z);
        acc.w += (v0.w + v1.w) + (v2.w + v3.w);
    }
    for (; j < deg; j++) {
        int s = g_csr[off + j];
        float4 v = ldh4(&g_half[s * HH + lane * 4]);
        acc.x += v.x; acc.y += v.y; acc.z += v.z; acc.w += v.w;
    }

    acc.x *= di; acc.y *= di; acc.z *= di; acc.w *= di;
    *(float4*)&g_bufB[wid * HH + lane * 4] = acc;
}

// bufB = relu(bufB @ W2 + b2), in place. f32x2 math, 2-pass 32KB smem.
__global__ void k_gemm2b(const float* __restrict__ W, const float* __restrict__ b2) {
    __shared__ float sW[64 * HH];
    int t = threadIdx.x;
    int lane = t & 31, warp = t >> 5;
    int nb = blockIdx.x * 32 + warp * 4;

    unsigned long long acc[4][2];
    #pragma unroll
    for (int n = 0; n < 4; n++) { acc[n][0] = 0ull; acc[n][1] = 0ull; }

    int nidx[4];
    #pragma unroll
    for (int n = 0; n < 4; n++) {
        int node = nb + n;
        nidx[n] = node < NN ? node : NN - 1;
    }

    for (int p = 0; p < 2; p++) {
        for (int i = t * 4; i < 64 * HH; i += blockDim.x * 4)
            *(float4*)&sW[i] = *(const float4*)&W[p * 64 * HH + i];
        __syncthreads();
        for (int k = 0; k < 64; k += 4) {
            float4 h[4];
            #pragma unroll
            for (int n = 0; n < 4; n++)
                h[n] = *(const float4*)&g_bufB[nidx[n] * HH + p * 64 + k];
            #pragma unroll
            for (int kk = 0; kk < 4; kk++) {
                ulonglong2 w = *(const ulonglong2*)&sW[(k + kk) * HH + lane * 4];
                #pragma unroll
                for (int n = 0; n < 4; n++) {
                    float hv = kk == 0 ? h[n].x : kk == 1 ? h[n].y : kk == 2 ? h[n].z : h[n].w;
                    unsigned long long hh = pack2(hv);
                    acc[n][0] = fma2(hh, w.x, acc[n][0]);
                    acc[n][1] = fma2(hh, w.y, acc[n][1]);
                }
            }
        }
        __syncthreads();
    }
    float4 bv = *(const float4*)&b2[lane * 4];
    #pragma unroll
    for (int n = 0; n < 4; n++) {
        int node = nb + n;
        if (node < NN) {
            float2 lo = unpack2(acc[n][0]);
            float2 hi = unpack2(acc[n][1]);
            float4 v;
            v.x = fmaxf(lo.x + bv.x, 0.f);
            v.y = fmaxf(lo.y + bv.y, 0.f);
            v.z = fmaxf(hi.x + bv.z, 0.f);
            v.w = fmaxf(hi.y + bv.w, 0.f);
            *(float4*)&g_bufB[node * HH + lane * 4] = v;
        }
    }
}

// One block (128 thr) per graph: sorted-batch segmented mean + both heads.
__global__ void k_poolhead(const int* __restrict__ batch,
                           const float* __restrict__ Wlab, const float* __restrict__ blab,
                           const float* __restrict__ Wd1, const float* __restrict__ bd1,
                           const float* __restrict__ Wd2, const float* __restrict__ bd2,
                           float* __restrict__ out) {
    __shared__ float p[HH];
    __shared__ float hid[64];
    __shared__ float warpsum[4];
    int g = blockIdx.x, t = threadIdx.x;

    int lo = 0, hi = NN;
    while (lo < hi) { int m = (lo + hi) >> 1; if (batch[m] < g) lo = m + 1; else hi = m; }
    int start = lo;
    hi = NN;
    while (lo < hi) { int m = (lo + hi) >> 1; if (batch[m] < g + 1) lo = m + 1; else hi = m; }
    int end = lo;

    float s = 0.f;
    for (int n = start; n < end; n++) s += g_bufB[n * HH + t];
    float c = fmaxf((float)(end - start), 1.0f);
    float pv = s / c;
    p[t] = pv;

    float l = pv * Wlab[t];
    #pragma unroll
    for (int o = 16; o; o >>= 1) l += __shfl_xor_sync(0xffffffffu, l, o);
    if ((t & 31) == 0) warpsum[t >> 5] = l;
    __syncthreads();

    if (t < 64) {
        float h2 = bd1[t];
        #pragma unroll 4
        for (int k = 0; k < HH; k++) h2 += p[k] * Wd1[k * 64 + t];
        hid[t] = fmaxf(h2, 0.f);
    }
    __syncthreads();

    if (t == 0) {
        float z = warpsum[0] + warpsum[1] + warpsum[2] + warpsum[3] + blab[0];
        out[g] = 1.0f / (1.0f + expf(-z));
    }
    if (t < 2) {
        float s2 = bd2[t];
        #pragma unroll
        for (int k = 0; k < 64; k++) s2 += hid[k] * Wd2[k * 2 + t];
        out[GG + g * 2 + t] = s2;
    }
}

extern "C" void kernel_launch(void* const* d_in, const int* in_sizes, int n_in,
                              void* d_out, int out_size) {
    const float* x     = (const float*)d_in[0];
    const int*   ei    = (const int*)d_in[1];     // int32 (JAX x64 disabled)
    const int*   batch = (const int*)d_in[2];     // int32
    const float* W1    = (const float*)d_in[3];
    const float* b1    = (const float*)d_in[4];
    const float* W2    = (const float*)d_in[5];
    const float* b2    = (const float*)d_in[6];
    const float* Wlab  = (const float*)d_in[7];
    const float* blab  = (const float*)d_in[8];
    const float* Wd1   = (const float*)d_in[9];
    const float* bd1   = (const float*)d_in[10];
    const float* Wd2   = (const float*)d_in[11];
    const float* bd2   = (const float*)d_in[12];
    float* out = (float*)d_out;

    const int T = 256;
    // CSR build + norms
    k_init<<<(NN + T - 1) / T, T>>>();
    k_deg<<<(EE + T - 1) / T, T>>>(ei);
    k_bsum<<<NBLK, T>>>();
    k_bscan<<<1, 64>>>();
    k_offsets<<<NBLK, T>>>();
    k_fill<<<(EE + T - 1) / T, T>>>(ei);

    // layer 1: aggregate raw 16-dim features, then W1 (commutation)
    k_prex<<<(NN * 8 + T - 1) / T, T>>>(x);
    k_agg16<<<(NN * 32 + T - 1) / T, T>>>(W1, b1);

    // layer 2: aggregate h1', then W2 in place
    k_agg128<<<(NN * 32 + T - 1) / T, T>>>();
    k_gemm2b<<<(NN + 31) / 32, T>>>(W2, b2);

    // pooling + heads
    k_poolhead<<<GG, HH>>>(batch, Wlab, blab, Wd1, bd1, Wd2, bd2, out);
}

// round 9
// speedup vs baseline: 2.0713x; 1.1403x over previous
#include <cuda_runtime.h>
#include <cuda_fp16.h>
#include <cstdint>
#include <math.h>

#define NN 50000
#define EE 1600000
#define GG 512
#define INF 16
#define HH 128
#define NBLK 49   // ceil(50000/1024)

// ---- scratch (static device memory; no allocation anywhere) ----
__device__ __half g_x16[NN * INF];  // dinv-prescaled input features
__device__ __half g_half[NN * HH];  // dinv-prescaled h1 (gather source, layer 2)
__device__ __half g_aggh[NN * HH];  // layer-2 aggregate, fp16 (GEMM A operand)
__device__ __half g_w2h[HH * HH];   // W2 in fp16
__device__ float  g_bufB[NN * HH];  // layer-2 output fp32 (pool input)
__device__ int    g_degi[NN];       // zeroed at end of every call (and statically)
__device__ int    g_off[NN];
__device__ int    g_cur[NN];
__device__ int    g_csr[EE];
__device__ float  g_dinv[NN];
__device__ int    g_bsum[NBLK];

// ---------- helpers ----------
__device__ __forceinline__ float4 ldh4(const __half* p) {
    uint2 u = *(const uint2*)p;
    __half2 a, b;
    *(unsigned*)&a = u.x; *(unsigned*)&b = u.y;
    float2 fa = __half22float2(a), fb = __half22float2(b);
    return make_float4(fa.x, fa.y, fb.x, fb.y);
}
__device__ __forceinline__ void sth4(__half* p, float4 v) {
    __half2 a = __floats2half2_rn(v.x, v.y);
    __half2 b = __floats2half2_rn(v.z, v.w);
    uint2 u;
    u.x = *(unsigned*)&a; u.y = *(unsigned*)&b;
    *(uint2*)p = u;
}
__device__ __forceinline__ void ldmx4t(unsigned& r0, unsigned& r1, unsigned& r2,
                                       unsigned& r3, const void* sp) {
    unsigned addr = (unsigned)__cvta_generic_to_shared(sp);
    asm volatile("ldmatrix.sync.aligned.m8n8.x4.trans.shared.b16 {%0,%1,%2,%3}, [%4];"
                 : "=r"(r0), "=r"(r1), "=r"(r2), "=r"(r3) : "r"(addr));
}
__device__ __forceinline__ void mma16816(float* c, unsigned a0, unsigned a1,
                                         unsigned a2, unsigned a3,
                                         unsigned b0, unsigned b1) {
    asm volatile("mma.sync.aligned.m16n8k16.row.col.f32.f16.f16.f32 "
                 "{%0,%1,%2,%3}, {%4,%5,%6,%7}, {%8,%9}, {%0,%1,%2,%3};"
                 : "+f"(c[0]), "+f"(c[1]), "+f"(c[2]), "+f"(c[3])
                 : "r"(a0), "r"(a1), "r"(a2), "r"(a3), "r"(b0), "r"(b1));
}

// histogram of dst (g_degi assumed zero on entry — re-zeroed by k_poolhead)
__global__ void k_deg(const int* __restrict__ ei) {
    int e = blockIdx.x * blockDim.x + threadIdx.x;
    if (e < EE) atomicAdd(&g_degi[ei[EE + e]], 1);
}

// 49 blocks: partial sums of g_degi; also converts W2 -> fp16 (independent work)
__global__ void k_bsum(const float* __restrict__ W2) {
    for (int i = blockIdx.x * blockDim.x + threadIdx.x; i < HH * HH;
         i += gridDim.x * blockDim.x)
        g_w2h[i] = __float2half_rn(W2[i]);

    __shared__ int sred[256];
    int b = blockIdx.x, t = threadIdx.x;
    int base = b * 1024 + t * 4;
    int s = 0;
    if (base + 3 < NN) {
        int4 q = *(const int4*)&g_degi[base];
        s = q.x + q.y + q.z + q.w;
    } else {
        for (int i = 0; i < 4; i++) if (base + i < NN) s += g_degi[base + i];
    }
    sred[t] = s;
    __syncthreads();
    for (int o = 128; o; o >>= 1) {
        if (t < o) sred[t] += sred[t + o];
        __syncthreads();
    }
    if (t == 0) g_bsum[b] = sred[0];
}

// offsets + cursors + dinv + (fused) block-sum prefix + (fused) x prescale->fp16
__global__ void k_offsets(const float* __restrict__ x) {
    __shared__ int spart[256];
    __shared__ int sb[64];
    __shared__ int sboff;
    int b = blockIdx.x, t = threadIdx.x;
    int base = b * 1024 + t * 4;
    int d0 = 0, d1 = 0, d2 = 0, d3 = 0;
    if (base + 3 < NN) {
        int4 q = *(const int4*)&g_degi[base];
        d0 = q.x; d1 = q.y; d2 = q.z; d3 = q.w;
    } else {
        if (base + 0 < NN) d0 = g_degi[base + 0];
        if (base + 1 < NN) d1 = g_degi[base + 1];
        if (base + 2 < NN) d2 = g_degi[base + 2];
        if (base + 3 < NN) d3 = g_degi[base + 3];
    }
    int tot = d0 + d1 + d2 + d3;
    spart[t] = tot;
    if (t < NBLK) sb[t] = g_bsum[t]; else if (t < 64) sb[t] = 0;
    __syncthreads();
    for (int o = 1; o < 256; o <<= 1) {
        int x2 = (t >= o) ? spart[t - o] : 0;
        __syncthreads();
        spart[t] += x2;
        __syncthreads();
    }
    if (t < 32) {
        int v = 0;
        for (int i = t; i < b; i += 32) v += sb[i];
        #pragma unroll
        for (int o = 16; o; o >>= 1) v += __shfl_xor_sync(0xffffffffu, v, o);
        if (t == 0) sboff = v;
    }
    __syncthreads();

    int off = sboff + spart[t] - tot;
    int dd[4] = {d0, d1, d2, d3};
    #pragma unroll
    for (int i = 0; i < 4; i++) {
        int idx = base + i;
        if (idx < NN) {
            g_off[idx] = off;
            g_cur[idx] = off;
            float di = rsqrtf((float)(dd[i] + 1));
            g_dinv[idx] = di;
            off += dd[i];
            #pragma unroll
            for (int q = 0; q < 8; q++) {
                float2 v = *(const float2*)&x[idx * INF + 2 * q];
                *(__half2*)&g_x16[idx * INF + 2 * q] =
                    __floats2half2_rn(v.x * di, v.y * di);
            }
        }
    }
}

__global__ void k_fill(const int* __restrict__ ei) {
    int e = blockIdx.x * blockDim.x + threadIdx.x;
    if (e >= EE) return;
    int s = ei[e];
    int d = ei[EE + e];
    int pos = atomicAdd(&g_cur[d], 1);
    g_csr[pos] = s;
}

// warp per node: a = di*(sum_src x'[s] + x'[n]) [16-dim], h1 = relu(a@W1+b1),
// store di*h1 fp16 -> g_half
__global__ void k_agg16(const float* __restrict__ W1, const float* __restrict__ b1) {
    __shared__ float sW[INF * HH];
    int t = threadIdx.x;
    for (int i = t; i < INF * HH; i += blockDim.x) sW[i] = W1[i];
    __syncthreads();

    int wid = (blockIdx.x * blockDim.x + t) >> 5;
    if (wid >= NN) return;
    int lane = t & 31;
    int grp = lane >> 3, p = lane & 7;
    int off = g_off[wid];
    int deg = g_degi[wid];
    float di = g_dinv[wid];

    float2 acc = make_float2(0.f, 0.f);
    if (grp == 0)
        acc = __half22float2(*(const __half2*)&g_x16[wid * INF + 2 * p]);

    for (int j = grp; j < deg; j += 4) {
        int s = g_csr[off + j];
        float2 v = __half22float2(*(const __half2*)&g_x16[s * INF + 2 * p]);
        acc.x += v.x; acc.y += v.y;
    }
    acc.x += __shfl_xor_sync(0xffffffffu, acc.x, 8);
    acc.y += __shfl_xor_sync(0xffffffffu, acc.y, 8);
    acc.x += __shfl_xor_sync(0xffffffffu, acc.x, 16);
    acc.y += __shfl_xor_sync(0xffffffffu, acc.y, 16);
    acc.x *= di; acc.y *= di;

    float4 out = *(const float4*)&b1[lane * 4];
    #pragma unroll
    for (int k = 0; k < 8; k++) {
        float ax = __shfl_sync(0xffffffffu, acc.x, k);
        float ay = __shfl_sync(0xffffffffu, acc.y, k);
        float4 w0 = *(const float4*)&sW[(2 * k) * HH + lane * 4];
        float4 w1 = *(const float4*)&sW[(2 * k + 1) * HH + lane * 4];
        out.x += ax * w0.x + ay * w1.x;
        out.y += ax * w0.y + ay * w1.y;
        out.z += ax * w0.z + ay * w1.z;
        out.w += ax * w0.w + ay * w1.w;
    }
    out.x = fmaxf(out.x, 0.f) * di;
    out.y = fmaxf(out.y, 0.f) * di;
    out.z = fmaxf(out.z, 0.f) * di;
    out.w = fmaxf(out.w, 0.f) * di;
    sth4(&g_half[wid * HH + lane * 4], out);
}

// warp per node: g_aggh[n] = fp16( di * (sum_src h1'[s] + h1'[n]) )
__global__ void k_agg128() {
    int wid = (blockIdx.x * blockDim.x + threadIdx.x) >> 5;
    int lane = threadIdx.x & 31;
    if (wid >= NN) return;
    int off = g_off[wid];
    int deg = g_degi[wid];
    float di = g_dinv[wid];

    float4 acc = ldh4(&g_half[wid * HH + lane * 4]);

    int j = 0;
    for (; j + 4 <= deg; j += 4) {
        int s0 = g_csr[off + j + 0];
        int s1 = g_csr[off + j + 1];
        int s2 = g_csr[off + j + 2];
        int s3 = g_csr[off + j + 3];
        float4 v0 = ldh4(&g_half[s0 * HH + lane * 4]);
        float4 v1 = ldh4(&g_half[s1 * HH + lane * 4]);
        float4 v2 = ldh4(&g_half[s2 * HH + lane * 4]);
        float4 v3 = ldh4(&g_half[s3 * HH + lane * 4]);
        acc.x += (v0.x + v1.x) + (v2.x + v3.x);
        acc.y += (v0.y + v1.y) + (v2.y + v3.y);
        acc.z += (v0.z + v1.z) + (v2.z + v3.z);
        acc.w += (v0.w + v1.w) + (v2.w + v3.w);
    }
    for (; j < deg; j++) {
        int s = g_csr[off + j];
        float4 v = ldh4(&g_half[s * HH + lane * 4]);
        acc.x += v.x; acc.y += v.y; acc.z += v.z; acc.w += v.w;
    }

    acc.x *= di; acc.y *= di; acc.z *= di; acc.w *= di;
    sth4(&g_aggh[wid * HH + lane * 4], acc);
}

// Tensor-core GEMM: bufB = relu(g_aggh @ W2h + b2).
// Block = 256 thr (8 warps), each warp: m16 x n128 x k128. 128 nodes/block.
__global__ void k_gemm2t(const float* __restrict__ b2) {
    __shared__ __align__(16) __half sB[HH][HH + 8];
    int t = threadIdx.x, lane = t & 31, warp = t >> 5;

    // stage W2 fp16 (2048 uint4)
    for (int i = t; i < 2048; i += 256) {
        int row = i >> 4, col = (i & 15) * 8;
        *(uint4*)&sB[row][col] = ((const uint4*)g_w2h)[i];
    }
    __syncthreads();

    int r0 = blockIdx.x * 128 + warp * 16 + (lane >> 2);
    int r1 = r0 + 8;
    int tg = lane & 3;
    long rl0 = (long)min(r0, NN - 1) * HH;
    long rl1 = (long)min(r1, NN - 1) * HH;

    float acc[16][4];
    #pragma unroll
    for (int f = 0; f < 16; f++)
        acc[f][0] = acc[f][1] = acc[f][2] = acc[f][3] = 0.f;

    #pragma unroll
    for (int k = 0; k < HH; k += 16) {
        unsigned a0 = *(const unsigned*)&g_aggh[rl0 + k + 2 * tg];
        unsigned a1 = *(const unsigned*)&g_aggh[rl1 + k + 2 * tg];
        unsigned a2 = *(const unsigned*)&g_aggh[rl0 + k + 8 + 2 * tg];
        unsigned a3 = *(const unsigned*)&g_aggh[rl1 + k + 8 + 2 * tg];
        #pragma unroll
        for (int nc = 0; nc < 8; nc++) {
            unsigned b0, b1, b2r, b3;
            ldmx4t(b0, b1, b2r, b3,
                   &sB[k + (lane & 15)][nc * 16 + ((lane >> 4) << 3)]);
            mma16816(acc[2 * nc + 0], a0, a1, a2, a3, b0, b1);
            mma16816(acc[2 * nc + 1], a0, a1, a2, a3, b2r, b3);
        }
    }

    #pragma unroll
    for (int f = 0; f < 16; f++) {
        int col = f * 8 + 2 * tg;
        float2 bias = *(const float2*)&b2[col];
        if (r0 < NN) {
            float2 o = make_float2(fmaxf(acc[f][0] + bias.x, 0.f),
                                   fmaxf(acc[f][1] + bias.y, 0.f));
            *(float2*)&g_bufB[(long)r0 * HH + col] = o;
        }
        if (r1 < NN) {
            float2 o = make_float2(fmaxf(acc[f][2] + bias.x, 0.f),
                                   fmaxf(acc[f][3] + bias.y, 0.f));
            *(float2*)&g_bufB[(long)r1 * HH + col] = o;
        }
    }
}

// One block (128 thr) per graph: segmented mean + heads. Also re-zeroes g_degi.
__global__ void k_poolhead(const int* __restrict__ batch,
                           const float* __restrict__ Wlab, const float* __restrict__ blab,
                           const float* __restrict__ Wd1, const float* __restrict__ bd1,
                           const float* __restrict__ Wd2, const float* __restrict__ bd2,
                           float* __restrict__ out) {
    __shared__ float p[HH];
    __shared__ float hid[64];
    __shared__ float warpsum[4];
    int g = blockIdx.x, t = threadIdx.x;

    int gi = g * HH + t;                 // 512*128 = 65536 >= NN
    if (gi < NN) g_degi[gi] = 0;         // replay-safe re-zero for next call

    int lo = 0, hi = NN;
    while (lo < hi) { int m = (lo + hi) >> 1; if (batch[m] < g) lo = m + 1; else hi = m; }
    int start = lo;
    hi = NN;
    while (lo < hi) { int m = (lo + hi) >> 1; if (batch[m] < g + 1) lo = m + 1; else hi = m; }
    int end = lo;

    float s = 0.f;
    for (int n = start; n < end; n++) s += g_bufB[n * HH + t];
    float c = fmaxf((float)(end - start), 1.0f);
    float pv = s / c;
    p[t] = pv;

    float l = pv * Wlab[t];
    #pragma unroll
    for (int o = 16; o; o >>= 1) l += __shfl_xor_sync(0xffffffffu, l, o);
    if ((t & 31) == 0) warpsum[t >> 5] = l;
    __syncthreads();

    if (t < 64) {
        float h2 = bd1[t];
        #pragma unroll 4
        for (int k = 0; k < HH; k++) h2 += p[k] * Wd1[k * 64 + t];
        hid[t] = fmaxf(h2, 0.f);
    }
    __syncthreads();

    if (t == 0) {
        float z = warpsum[0] + warpsum[1] + warpsum[2] + warpsum[3] + blab[0];
        out[g] = 1.0f / (1.0f + expf(-z));
    }
    if (t < 2) {
        float s2 = bd2[t];
        #pragma unroll
        for (int k = 0; k < 64; k++) s2 += hid[k] * Wd2[k * 2 + t];
        out[GG + g * 2 + t] = s2;
    }
}

extern "C" void kernel_launch(void* const* d_in, const int* in_sizes, int n_in,
                              void* d_out, int out_size) {
    const float* x     = (const float*)d_in[0];
    const int*   ei    = (const int*)d_in[1];     // int32 (JAX x64 disabled)
    const int*   batch = (const int*)d_in[2];     // int32
    const float* W1    = (const float*)d_in[3];
    const float* b1    = (const float*)d_in[4];
    const float* W2    = (const float*)d_in[5];
    const float* b2    = (const float*)d_in[6];
    const float* Wlab  = (const float*)d_in[7];
    const float* blab  = (const float*)d_in[8];
    const float* Wd1   = (const float*)d_in[9];
    const float* bd1   = (const float*)d_in[10];
    const float* Wd2   = (const float*)d_in[11];
    const float* bd2   = (const float*)d_in[12];
    float* out = (float*)d_out;

    const int T = 256;
    k_deg<<<(EE + T - 1) / T, T>>>(ei);
    k_bsum<<<NBLK, T>>>(W2);                 // + W2 -> fp16
    k_offsets<<<NBLK, T>>>(x);               // + block-sum prefix + x prescale
    k_fill<<<(EE + T - 1) / T, T>>>(ei);

    k_agg16<<<(NN * 32 + T - 1) / T, T>>>(W1, b1);
    k_agg128<<<(NN * 32 + T - 1) / T, T>>>();
    k_gemm2t<<<(NN + 127) / 128, T>>>(b2);

    k_poolhead<<<GG, HH>>>(batch, Wlab, blab, Wd1, bd1, Wd2, bd2, out);
}

// round 10
// speedup vs baseline: 2.2039x; 1.0640x over previous
#include <cuda_runtime.h>
#include <cuda_fp16.h>
#include <cstdint>
#include <math.h>

#define NN 50000
#define EE 1600000
#define GG 512
#define INF 16
#define HH 128
#define NBLK 49   // ceil(50000/1024)

// ---- scratch (static device memory; no allocation anywhere) ----
__device__ __half g_x16[NN * INF];  // dinv-prescaled input features
__device__ __half g_half[NN * HH];  // dinv-prescaled h1; later reused as fp16 h2 out
__device__ __half g_aggh[NN * HH];  // layer-2 aggregate, fp16 (GEMM A operand)
__device__ __half g_w2h[HH * HH];   // W2 in fp16
__device__ int    g_degi[NN];       // zeroed at end of every call (and statically)
__device__ int    g_off[NN];
__device__ int    g_csr[EE];        // src ids grouped by dst
__device__ int    g_rank[EE];       // edge rank within its dst bucket
__device__ float  g_dinv[NN];
__device__ int    g_bsum[NBLK];

// ---------- helpers ----------
__device__ __forceinline__ float4 ldh4(const __half* p) {
    uint2 u = *(const uint2*)p;
    __half2 a, b;
    *(unsigned*)&a = u.x; *(unsigned*)&b = u.y;
    float2 fa = __half22float2(a), fb = __half22float2(b);
    return make_float4(fa.x, fa.y, fb.x, fb.y);
}
__device__ __forceinline__ void sth4(__half* p, float4 v) {
    __half2 a = __floats2half2_rn(v.x, v.y);
    __half2 b = __floats2half2_rn(v.z, v.w);
    uint2 u;
    u.x = *(unsigned*)&a; u.y = *(unsigned*)&b;
    *(uint2*)p = u;
}
__device__ __forceinline__ void ldmx4t(unsigned& r0, unsigned& r1, unsigned& r2,
                                       unsigned& r3, const void* sp) {
    unsigned addr = (unsigned)__cvta_generic_to_shared(sp);
    asm volatile("ldmatrix.sync.aligned.m8n8.x4.trans.shared.b16 {%0,%1,%2,%3}, [%4];"
                 : "=r"(r0), "=r"(r1), "=r"(r2), "=r"(r3) : "r"(addr));
}
__device__ __forceinline__ void mma16816(float* c, unsigned a0, unsigned a1,
                                         unsigned a2, unsigned a3,
                                         unsigned b0, unsigned b1) {
    asm volatile("mma.sync.aligned.m16n8k16.row.col.f32.f16.f16.f32 "
                 "{%0,%1,%2,%3}, {%4,%5,%6,%7}, {%8,%9}, {%0,%1,%2,%3};"
                 : "+f"(c[0]), "+f"(c[1]), "+f"(c[2]), "+f"(c[3])
                 : "r"(a0), "r"(a1), "r"(a2), "r"(a3), "r"(b0), "r"(b1));
}

// histogram of dst; rank = position of edge within its dst bucket
__global__ void k_deg(const int* __restrict__ ei) {
    int e = blockIdx.x * blockDim.x + threadIdx.x;
    if (e < EE) g_rank[e] = atomicAdd(&g_degi[ei[EE + e]], 1);
}

// 49 blocks: partial sums of g_degi; also converts W2 -> fp16 (independent work)
__global__ void k_bsum(const float* __restrict__ W2) {
    for (int i = blockIdx.x * blockDim.x + threadIdx.x; i < HH * HH;
         i += gridDim.x * blockDim.x)
        g_w2h[i] = __float2half_rn(W2[i]);

    __shared__ int sred[256];
    int b = blockIdx.x, t = threadIdx.x;
    int base = b * 1024 + t * 4;
    int s = 0;
    if (base + 3 < NN) {
        int4 q = *(const int4*)&g_degi[base];
        s = q.x + q.y + q.z + q.w;
    } else {
        for (int i = 0; i < 4; i++) if (base + i < NN) s += g_degi[base + i];
    }
    sred[t] = s;
    __syncthreads();
    for (int o = 128; o; o >>= 1) {
        if (t < o) sred[t] += sred[t + o];
        __syncthreads();
    }
    if (t == 0) g_bsum[b] = sred[0];
}

// offsets + dinv + (fused) block-sum prefix + (fused) x prescale->fp16
__global__ void k_offsets(const float* __restrict__ x) {
    __shared__ int spart[256];
    __shared__ int sb[64];
    __shared__ int sboff;
    int b = blockIdx.x, t = threadIdx.x;
    int base = b * 1024 + t * 4;
    int d0 = 0, d1 = 0, d2 = 0, d3 = 0;
    if (base + 3 < NN) {
        int4 q = *(const int4*)&g_degi[base];
        d0 = q.x; d1 = q.y; d2 = q.z; d3 = q.w;
    } else {
        if (base + 0 < NN) d0 = g_degi[base + 0];
        if (base + 1 < NN) d1 = g_degi[base + 1];
        if (base + 2 < NN) d2 = g_degi[base + 2];
        if (base + 3 < NN) d3 = g_degi[base + 3];
    }
    int tot = d0 + d1 + d2 + d3;
    spart[t] = tot;
    if (t < NBLK) sb[t] = g_bsum[t]; else if (t < 64) sb[t] = 0;
    __syncthreads();
    for (int o = 1; o < 256; o <<= 1) {
        int x2 = (t >= o) ? spart[t - o] : 0;
        __syncthreads();
        spart[t] += x2;
        __syncthreads();
    }
    if (t < 32) {
        int v = 0;
        for (int i = t; i < b; i += 32) v += sb[i];
        #pragma unroll
        for (int o = 16; o; o >>= 1) v += __shfl_xor_sync(0xffffffffu, v, o);
        if (t == 0) sboff = v;
    }
    __syncthreads();

    int off = sboff + spart[t] - tot;
    int dd[4] = {d0, d1, d2, d3};
    #pragma unroll
    for (int i = 0; i < 4; i++) {
        int idx = base + i;
        if (idx < NN) {
            g_off[idx] = off;
            float di = rsqrtf((float)(dd[i] + 1));
            g_dinv[idx] = di;
            off += dd[i];
            #pragma unroll
            for (int q = 0; q < 8; q++) {
                float2 v = *(const float2*)&x[idx * INF + 2 * q];
                *(__half2*)&g_x16[idx * INF + 2 * q] =
                    __floats2half2_rn(v.x * di, v.y * di);
            }
        }
    }
}

// atomic-free CSR fill: pos = g_off[dst] + rank
__global__ void k_fill(const int* __restrict__ ei) {
    int e = blockIdx.x * blockDim.x + threadIdx.x;
    if (e >= EE) return;
    int s = ei[e];
    int d = ei[EE + e];
    g_csr[g_off[d] + g_rank[e]] = s;
}

// warp per node: a = di*(sum_src x'[s] + x'[n]) [16-dim], h1 = relu(a@W1+b1),
// store di*h1 fp16 -> g_half
__global__ void k_agg16(const float* __restrict__ W1, const float* __restrict__ b1) {
    __shared__ float sW[INF * HH];
    int t = threadIdx.x;
    for (int i = t; i < INF * HH; i += blockDim.x) sW[i] = W1[i];
    __syncthreads();

    int wid = (blockIdx.x * blockDim.x + t) >> 5;
    if (wid >= NN) return;
    int lane = t & 31;
    int grp = lane >> 3, p = lane & 7;
    int off = g_off[wid];
    int deg = g_degi[wid];
    float di = g_dinv[wid];

    float2 acc = make_float2(0.f, 0.f);
    if (grp == 0)
        acc = __half22float2(*(const __half2*)&g_x16[wid * INF + 2 * p]);

    for (int j = grp; j < deg; j += 4) {
        int s = g_csr[off + j];
        float2 v = __half22float2(*(const __half2*)&g_x16[s * INF + 2 * p]);
        acc.x += v.x; acc.y += v.y;
    }
    acc.x += __shfl_xor_sync(0xffffffffu, acc.x, 8);
    acc.y += __shfl_xor_sync(0xffffffffu, acc.y, 8);
    acc.x += __shfl_xor_sync(0xffffffffu, acc.x, 16);
    acc.y += __shfl_xor_sync(0xffffffffu, acc.y, 16);
    acc.x *= di; acc.y *= di;

    float4 out = *(const float4*)&b1[lane * 4];
    #pragma unroll
    for (int k = 0; k < 8; k++) {
        float ax = __shfl_sync(0xffffffffu, acc.x, k);
        float ay = __shfl_sync(0xffffffffu, acc.y, k);
        float4 w0 = *(const float4*)&sW[(2 * k) * HH + lane * 4];
        float4 w1 = *(const float4*)&sW[(2 * k + 1) * HH + lane * 4];
        out.x += ax * w0.x + ay * w1.x;
        out.y += ax * w0.y + ay * w1.y;
        out.z += ax * w0.z + ay * w1.z;
        out.w += ax * w0.w + ay * w1.w;
    }
    out.x = fmaxf(out.x, 0.f) * di;
    out.y = fmaxf(out.y, 0.f) * di;
    out.z = fmaxf(out.z, 0.f) * di;
    out.w = fmaxf(out.w, 0.f) * di;
    sth4(&g_half[wid * HH + lane * 4], out);
}

// warp per node: g_aggh[n] = fp16( di * (sum_src h1'[s] + h1'[n]) )
__global__ void k_agg128() {
    int wid = (blockIdx.x * blockDim.x + threadIdx.x) >> 5;
    int lane = threadIdx.x & 31;
    if (wid >= NN) return;
    int off = g_off[wid];
    int deg = g_degi[wid];
    float di = g_dinv[wid];

    float4 acc = ldh4(&g_half[wid * HH + lane * 4]);

    int j = 0;
    for (; j + 4 <= deg; j += 4) {
        int s0 = g_csr[off + j + 0];
        int s1 = g_csr[off + j + 1];
        int s2 = g_csr[off + j + 2];
        int s3 = g_csr[off + j + 3];
        float4 v0 = ldh4(&g_half[s0 * HH + lane * 4]);
        float4 v1 = ldh4(&g_half[s1 * HH + lane * 4]);
        float4 v2 = ldh4(&g_half[s2 * HH + lane * 4]);
        float4 v3 = ldh4(&g_half[s3 * HH + lane * 4]);
        acc.x += (v0.x + v1.x) + (v2.x + v3.x);
        acc.y += (v0.y + v1.y) + (v2.y + v3.y);
        acc.z += (v0.z + v1.z) + (v2.z + v3.z);
        acc.w += (v0.w + v1.w) + (v2.w + v3.w);
    }
    for (; j < deg; j++) {
        int s = g_csr[off + j];
        float4 v = ldh4(&g_half[s * HH + lane * 4]);
        acc.x += v.x; acc.y += v.y; acc.z += v.z; acc.w += v.w;
    }

    acc.x *= di; acc.y *= di; acc.z *= di; acc.w *= di;
    sth4(&g_aggh[wid * HH + lane * 4], acc);
}

// Tensor-core GEMM: g_half = fp16(relu(g_aggh @ W2h + b2)).
// Block = 256 thr (8 warps), each warp m16 x n128 x k128; 128 nodes/block.
__global__ void k_gemm2t(const float* __restrict__ b2) {
    __shared__ __align__(16) __half sB[HH][HH + 8];
    int t = threadIdx.x, lane = t & 31, warp = t >> 5;

    for (int i = t; i < 2048; i += 256) {
        int row = i >> 4, col = (i & 15) * 8;
        *(uint4*)&sB[row][col] = ((const uint4*)g_w2h)[i];
    }
    __syncthreads();

    int r0 = blockIdx.x * 128 + warp * 16 + (lane >> 2);
    int r1 = r0 + 8;
    int tg = lane & 3;
    long rl0 = (long)min(r0, NN - 1) * HH;
    long rl1 = (long)min(r1, NN - 1) * HH;

    float acc[16][4];
    #pragma unroll
    for (int f = 0; f < 16; f++)
        acc[f][0] = acc[f][1] = acc[f][2] = acc[f][3] = 0.f;

    #pragma unroll
    for (int k = 0; k < HH; k += 16) {
        unsigned a0 = *(const unsigned*)&g_aggh[rl0 + k + 2 * tg];
        unsigned a1 = *(const unsigned*)&g_aggh[rl1 + k + 2 * tg];
        unsigned a2 = *(const unsigned*)&g_aggh[rl0 + k + 8 + 2 * tg];
        unsigned a3 = *(const unsigned*)&g_aggh[rl1 + k + 8 + 2 * tg];
        #pragma unroll
        for (int nc = 0; nc < 8; nc++) {
            unsigned b0, b1, b2r, b3;
            ldmx4t(b0, b1, b2r, b3,
                   &sB[k + (lane & 15)][nc * 16 + ((lane >> 4) << 3)]);
            mma16816(acc[2 * nc + 0], a0, a1, a2, a3, b0, b1);
            mma16816(acc[2 * nc + 1], a0, a1, a2, a3, b2r, b3);
        }
    }

    #pragma unroll
    for (int f = 0; f < 16; f++) {
        int col = f * 8 + 2 * tg;
        float2 bias = *(const float2*)&b2[col];
        if (r0 < NN) {
            *(__half2*)&g_half[(long)r0 * HH + col] =
                __floats2half2_rn(fmaxf(acc[f][0] + bias.x, 0.f),
                                  fmaxf(acc[f][1] + bias.y, 0.f));
        }
        if (r1 < NN) {
            *(__half2*)&g_half[(long)r1 * HH + col] =
                __floats2half2_rn(fmaxf(acc[f][2] + bias.x, 0.f),
                                  fmaxf(acc[f][3] + bias.y, 0.f));
        }
    }
}

// One block (128 thr) per graph: segmented mean (fp16 in, fp32 acc) + heads.
// Also re-zeroes g_degi for the next replay.
__global__ void k_poolhead(const int* __restrict__ batch,
                           const float* __restrict__ Wlab, const float* __restrict__ blab,
                           const float* __restrict__ Wd1, const float* __restrict__ bd1,
                           const float* __restrict__ Wd2, const float* __restrict__ bd2,
                           float* __restrict__ out) {
    __shared__ float p[HH];
    __shared__ float hid[64];
    __shared__ float warpsum[4];
    int g = blockIdx.x, t = threadIdx.x;

    int gi = g * HH + t;                 // 512*128 = 65536 >= NN
    if (gi < NN) g_degi[gi] = 0;

    int lo = 0, hi = NN;
    while (lo < hi) { int m = (lo + hi) >> 1; if (batch[m] < g) lo = m + 1; else hi = m; }
    int start = lo;
    hi = NN;
    while (lo < hi) { int m = (lo + hi) >> 1; if (batch[m] < g + 1) lo = m + 1; else hi = m; }
    int end = lo;

    float s = 0.f;
    for (int n = start; n < end; n++) s += __half2float(g_half[n * HH + t]);
    float c = fmaxf((float)(end - start), 1.0f);
    float pv = s / c;
    p[t] = pv;

    float l = pv * Wlab[t];
    #pragma unroll
    for (int o = 16; o; o >>= 1) l += __shfl_xor_sync(0xffffffffu, l, o);
    if ((t & 31) == 0) warpsum[t >> 5] = l;
    __syncthreads();

    if (t < 64) {
        float h2 = bd1[t];
        #pragma unroll 4
        for (int k = 0; k < HH; k++) h2 += p[k] * Wd1[k * 64 + t];
        hid[t] = fmaxf(h2, 0.f);
    }
    __syncthreads();

    if (t == 0) {
        float z = warpsum[0] + warpsum[1] + warpsum[2] + warpsum[3] + blab[0];
        out[g] = 1.0f / (1.0f + expf(-z));
    }
    if (t < 2) {
        float s2 = bd2[t];
        #pragma unroll
        for (int k = 0; k < 64; k++) s2 += hid[k] * Wd2[k * 2 + t];
        out[GG + g * 2 + t] = s2;
    }
}

extern "C" void kernel_launch(void* const* d_in, const int* in_sizes, int n_in,
                              void* d_out, int out_size) {
    const float* x     = (const float*)d_in[0];
    const int*   ei    = (const int*)d_in[1];     // int32 (JAX x64 disabled)
    const int*   batch = (const int*)d_in[2];     // int32
    const float* W1    = (const float*)d_in[3];
    const float* b1    = (const float*)d_in[4];
    const float* W2    = (const float*)d_in[5];
    const float* b2    = (const float*)d_in[6];
    const float* Wlab  = (const float*)d_in[7];
    const float* blab  = (const float*)d_in[8];
    const float* Wd1   = (const float*)d_in[9];
    const float* bd1   = (const float*)d_in[10];
    const float* Wd2   = (const float*)d_in[11];
    const float* bd2   = (const float*)d_in[12];
    float* out = (float*)d_out;

    const int T = 256;
    k_deg<<<(EE + T - 1) / T, T>>>(ei);          // histogram + rank
    k_bsum<<<NBLK, T>>>(W2);                     // + W2 -> fp16
    k_offsets<<<NBLK, T>>>(x);                   // + prefix + x prescale
    k_fill<<<(EE + T - 1) / T, T>>>(ei);         // atomic-free

    k_agg16<<<(NN * 32 + T - 1) / T, T>>>(W1, b1);
    k_agg128<<<(NN * 32 + T - 1) / T, T>>>();
    k_gemm2t<<<(NN + 127) / 128, T>>>(b2);

    k_poolhead<<<GG, HH>>>(batch, Wlab, blab, Wd1, bd1, Wd2, bd2, out);
}